// round 8
// baseline (speedup 1.0000x reference)
#include <cuda_runtime.h>
#include <cuda_bf16.h>
#include <cstdint>

// RNN_438086664357: h_{t+1} = tanh(W [h_t ; x_t] + b)
// Round 8: Z precomputed (67% tensor kernel); per-step kernel now 8 warps
// (2/SMSP), m32n32 warp tiles, j-split over wk(4), intra-CTA smem reduction.

#define TSTEPS 256
#define BATCH  256
#define DH     1024
#define DIN    1024
#define KTOT   2048
#define KC     64
#define NCH    16              // K=1024 / 64

typedef unsigned int u32;

// step stage: Ahi 4K | Alo 4K | Whi 8K | Wlo 8K
#define SOFF_ALO  4096
#define SOFF_WHI  8192
#define SOFF_WLO  16384
#define STG1      24576
#define SMEM1     (3 * STG1)      // 72 KB (reduction reuses stage 0 area)

// precompute stage: Ahi 16K | Alo 16K | Whi 8K | Wlo 8K
#define SOFF2_ALO 16384
#define SOFF2_WHI 32768
#define SOFF2_WLO 40960
#define STG2      49152
#define SMEM2     (3 * STG2)      // 144 KB

// ---- device scratch ----
__device__ __nv_bfloat16 g_xhi[(size_t)TSTEPS * BATCH * DIN];
__device__ __nv_bfloat16 g_xlo[(size_t)TSTEPS * BATCH * DIN];
__device__ __nv_bfloat16 g_whi[(size_t)DH * KTOT];
__device__ __nv_bfloat16 g_wlo[(size_t)DH * KTOT];
__device__ __nv_bfloat16 g_hhi[2 * (size_t)BATCH * DH];
__device__ __nv_bfloat16 g_hlo[2 * (size_t)BATCH * DH];
__device__ float g_Z[(size_t)TSTEPS * BATCH * DH];

__device__ __forceinline__ u32 s2u(const void* p) {
    u32 a;
    asm("{ .reg .u64 t; cvta.to.shared.u64 t, %1; cvt.u32.u64 %0, t; }"
        : "=r"(a) : "l"(p));
    return a;
}

#define CP16(sm, gp) asm volatile("cp.async.cg.shared.global [%0], [%1], 16;" :: "r"(sm), "l"(gp))
#define CP_COMMIT()  asm volatile("cp.async.commit_group;" ::: "memory")

__device__ __forceinline__ void ldsm4(u32 a, u32& r0, u32& r1, u32& r2, u32& r3) {
    asm volatile("ldmatrix.sync.aligned.m8n8.x4.shared.b16 {%0,%1,%2,%3}, [%4];"
                 : "=r"(r0), "=r"(r1), "=r"(r2), "=r"(r3) : "r"(a));
}

__device__ __forceinline__ void mma16816(float* c, const u32* a, u32 b0, u32 b1) {
    asm volatile(
        "mma.sync.aligned.m16n8k16.row.col.f32.bf16.bf16.f32 "
        "{%0,%1,%2,%3}, {%4,%5,%6,%7}, {%8,%9}, {%0,%1,%2,%3};"
        : "+f"(c[0]), "+f"(c[1]), "+f"(c[2]), "+f"(c[3])
        : "r"(a[0]), "r"(a[1]), "r"(a[2]), "r"(a[3]), "r"(b0), "r"(b1));
}

// ---- setup kernels ----
__global__ void split_w(const float* __restrict__ W) {
    int i = blockIdx.x * blockDim.x + threadIdx.x;
    float v = W[i];
    __nv_bfloat16 h = __float2bfloat16(v);
    g_whi[i] = h;
    g_wlo[i] = __float2bfloat16(v - __bfloat162float(h));
}

__global__ void split_x(const float* __restrict__ X) {
    size_t i = (size_t)blockIdx.x * blockDim.x + threadIdx.x;
    float v = X[i];
    __nv_bfloat16 h = __float2bfloat16(v);
    g_xhi[i] = h;
    g_xlo[i] = __float2bfloat16(v - __bfloat162float(h));
}

__global__ void init_out0(float* __restrict__ out0) {
    out0[blockIdx.x * blockDim.x + threadIdx.x] = 0.0f;
}

// ---- precompute Z = x @ Wx^T + b (proven: 67% tensor) ----
__global__ void __launch_bounds__(256, 1)
precompute_z(const float* __restrict__ bias)
{
    extern __shared__ char smem[];
    const u32 sb = s2u(smem);
    const int tid = threadIdx.x, wid = tid >> 5, lane = tid & 31;
    const int wm = wid & 3, wn = wid >> 2;
    const int n0 = blockIdx.x * 64;
    const int mg = blockIdx.y * 128;

    auto load_chunk = [&](int c, int s) {
        const u32 st = sb + s * STG2;
        const int ko = c * KC;
        #pragma unroll
        for (int i = 0; i < 4; i++) {
            int unit = tid + i * 256;
            int r = unit >> 3, g = unit & 7;
            u32 so = (u32)(r * 128 + ((g ^ (r & 7)) * 16));
            size_t go = (size_t)(mg + r) * DIN + ko + g * 8;
            CP16(st + so,             g_xhi + go);
            CP16(st + SOFF2_ALO + so, g_xlo + go);
        }
        #pragma unroll
        for (int i = 0; i < 2; i++) {
            int unit = tid + i * 256;
            int r = unit >> 3, g = unit & 7;
            u32 so = (u32)(r * 128 + ((g ^ (r & 7)) * 16));
            size_t go = (size_t)(n0 + r) * KTOT + DH + ko + g * 8;
            CP16(st + SOFF2_WHI + so, g_whi + go);
            CP16(st + SOFF2_WLO + so, g_wlo + go);
        }
        CP_COMMIT();
    };

    float c0[32], c1[32], c2[32];
    #pragma unroll
    for (int i = 0; i < 32; i++) { c0[i] = 0.f; c1[i] = 0.f; c2[i] = 0.f; }

    load_chunk(0, 0);
    load_chunk(1, 1);
    for (int c = 0; c < 16; c++) {
        if (c < 15) asm volatile("cp.async.wait_group 1;" ::: "memory");
        else        asm volatile("cp.async.wait_group 0;" ::: "memory");
        __syncthreads();
        const u32 st = sb + (c % 3) * STG2;
        #pragma unroll
        for (int j = 0; j < 4; j++) {
            u32 ah[2][4], al[2][4], bh[8], bl[8];
            #pragma unroll
            for (int tm = 0; tm < 2; tm++) {
                int row = wm * 32 + tm * 16 + (lane & 15);
                int g = j * 2 + (lane >> 4);
                u32 so = (u32)(row * 128 + ((g ^ (row & 7)) * 16));
                ldsm4(st + so,             ah[tm][0], ah[tm][1], ah[tm][2], ah[tm][3]);
                ldsm4(st + SOFF2_ALO + so, al[tm][0], al[tm][1], al[tm][2], al[tm][3]);
            }
            int rB = wn * 32 + (lane & 7) + ((lane >> 4) & 1) * 8;
            int gB = j * 2 + ((lane >> 3) & 1);
            #pragma unroll
            for (int q = 0; q < 2; q++) {
                int r = rB + q * 16;
                u32 so = (u32)(r * 128 + ((gB ^ (r & 7)) * 16));
                ldsm4(st + SOFF2_WHI + so, bh[q*4+0], bh[q*4+1], bh[q*4+2], bh[q*4+3]);
                ldsm4(st + SOFF2_WLO + so, bl[q*4+0], bl[q*4+1], bl[q*4+2], bl[q*4+3]);
            }
            #pragma unroll
            for (int tm = 0; tm < 2; tm++)
                #pragma unroll
                for (int nt = 0; nt < 4; nt++) {
                    int o = tm * 16 + nt * 4;
                    mma16816(c0 + o, ah[tm], bh[nt*2], bh[nt*2+1]);
                    mma16816(c1 + o, al[tm], bh[nt*2], bh[nt*2+1]);
                    mma16816(c2 + o, ah[tm], bl[nt*2], bl[nt*2+1]);
                }
        }
        if (c + 2 < 16) load_chunk(c + 2, (c + 2) % 3);
    }

    #pragma unroll
    for (int tm = 0; tm < 2; tm++)
        #pragma unroll
        for (int nt = 0; nt < 4; nt++) {
            const int col = n0 + wn * 32 + nt * 8 + (lane & 3) * 2;
            const float b0 = __ldg(bias + col), b1 = __ldg(bias + col + 1);
            #pragma unroll
            for (int hf = 0; hf < 2; hf++) {
                const int row = mg + wm * 32 + tm * 16 + (lane >> 2) + hf * 8;
                const int o = tm * 16 + nt * 4 + hf * 2;
                float z0 = c0[o]   + c1[o]   + c2[o]   + b0;
                float z1 = c0[o+1] + c1[o+1] + c2[o+1] + b1;
                *(float2*)(g_Z + (size_t)row * DH + col) = make_float2(z0, z1);
            }
        }
}

// ---- per-step: s = h @ Wh^T (K=1024); h' = tanh(s + Z[t]) ----
// grid (16 n, 8 m); CTA tile (32m, 64n); 8 warps = wk(4) x wn(2),
// warp tile m32n32, j-split (j = wk) per KC chunk, smem reduction.
__global__ void __launch_bounds__(256, 1)
rnn_step(float* __restrict__ outNext, int t, int parity)
{
    extern __shared__ char smem[];
    const u32 sb = s2u(smem);
    const int tid = threadIdx.x, wid = tid >> 5, lane = tid & 31;
    const int wk = wid >> 1, wn = wid & 1;   // 4 k-groups x 2 n-halves
    const int n0 = blockIdx.x * 64, m0 = blockIdx.y * 32;

    float s[32];

    if (t > 0) {
        const __nv_bfloat16* Ahi0 = g_hhi + (size_t)parity * BATCH * DH;
        const __nv_bfloat16* Alo0 = g_hlo + (size_t)parity * BATCH * DH;
        const int lr = tid >> 3, lg = tid & 7;   // 256 thr: 32 rows x 8 groups

        auto load_chunk = [&](int c, int st_idx) {
            const u32 st = sb + st_idx * STG1;
            const int ko = c * KC;
            {   // A: 32 rows, 1 unit/thread per buffer
                u32 so = (u32)(lr * 128 + ((lg ^ (lr & 7)) * 16));
                size_t go = (size_t)(m0 + lr) * DH + ko + lg * 8;
                CP16(st + so,            Ahi0 + go);
                CP16(st + SOFF_ALO + so, Alo0 + go);
            }
            #pragma unroll
            for (int u = 0; u < 2; u++) {   // W: 64 rows, 2 units/thread
                int r = lr + u * 32;
                u32 so = (u32)(r * 128 + ((lg ^ (r & 7)) * 16));
                size_t go = (size_t)(n0 + r) * KTOT + ko + lg * 8;
                CP16(st + SOFF_WHI + so, g_whi + go);
                CP16(st + SOFF_WLO + so, g_wlo + go);
            }
            CP_COMMIT();
        };

        float c0[32], c1[32], c2[32];
        #pragma unroll
        for (int i = 0; i < 32; i++) { c0[i] = 0.f; c1[i] = 0.f; c2[i] = 0.f; }

        // per-warp constant address components (j = wk)
        const int aHi   = (lane >> 4);
        const int gA    = wk * 2 + aHi;
        const int bRow0 = wn * 32 + (lane & 7) + ((lane >> 4) & 1) * 8;
        const int gB    = wk * 2 + ((lane >> 3) & 1);

        load_chunk(0, 0);
        load_chunk(1, 1);
        for (int c = 0; c < NCH; c++) {
            if (c < NCH - 1) asm volatile("cp.async.wait_group 1;" ::: "memory");
            else             asm volatile("cp.async.wait_group 0;" ::: "memory");
            __syncthreads();
            const u32 st = sb + (c % 3) * STG1;

            u32 ah[2][4], al[2][4], bh[8], bl[8];
            #pragma unroll
            for (int tm = 0; tm < 2; tm++) {
                int row = tm * 16 + (lane & 15);
                u32 so = (u32)(row * 128 + ((gA ^ (row & 7)) * 16));
                ldsm4(st + so,            ah[tm][0], ah[tm][1], ah[tm][2], ah[tm][3]);
                ldsm4(st + SOFF_ALO + so, al[tm][0], al[tm][1], al[tm][2], al[tm][3]);
            }
            #pragma unroll
            for (int q = 0; q < 2; q++) {
                int r = bRow0 + q * 16;
                u32 so = (u32)(r * 128 + ((gB ^ (r & 7)) * 16));
                ldsm4(st + SOFF_WHI + so, bh[q*4+0], bh[q*4+1], bh[q*4+2], bh[q*4+3]);
                ldsm4(st + SOFF_WLO + so, bl[q*4+0], bl[q*4+1], bl[q*4+2], bl[q*4+3]);
            }
            #pragma unroll
            for (int tm = 0; tm < 2; tm++)
                #pragma unroll
                for (int nt = 0; nt < 4; nt++) {
                    int o = tm * 16 + nt * 4;
                    mma16816(c0 + o, ah[tm], bh[nt*2], bh[nt*2+1]);
                    mma16816(c1 + o, al[tm], bh[nt*2], bh[nt*2+1]);
                    mma16816(c2 + o, ah[tm], bl[nt*2], bl[nt*2+1]);
                }

            if (c + 2 < NCH) load_chunk(c + 2, (c + 2) % 3);
        }

        #pragma unroll
        for (int i = 0; i < 32; i++) s[i] = c0[i] + c1[i] + c2[i];

        // reduce across wk groups: groups 1..3 publish, group 0 folds
        float* red = (float*)smem;   // 3 * 2 * 32 * 32 floats = 24 KB
        __syncthreads();             // stages fully consumed
        if (wk > 0) {
            float* dst = red + (((wk - 1) * 2 + wn) * 32 + lane) * 32;
            #pragma unroll
            for (int i = 0; i < 8; i++)
                *(float4*)(dst + i * 4) =
                    make_float4(s[i*4], s[i*4+1], s[i*4+2], s[i*4+3]);
        }
        __syncthreads();
        if (wk == 0) {
            #pragma unroll
            for (int g = 0; g < 3; g++) {
                const float* src = red + ((g * 2 + wn) * 32 + lane) * 32;
                #pragma unroll
                for (int i = 0; i < 8; i++) {
                    float4 v = *(const float4*)(src + i * 4);
                    s[i*4] += v.x; s[i*4+1] += v.y; s[i*4+2] += v.z; s[i*4+3] += v.w;
                }
            }
        }
    } else {
        #pragma unroll
        for (int i = 0; i < 32; i++) s[i] = 0.f;
    }

    // epilogue (wk==0 warps only): h' = tanh(s + Z[t])
    if (wk == 0) {
        __nv_bfloat16* hh0 = g_hhi + (size_t)(parity ^ 1) * BATCH * DH;
        __nv_bfloat16* hl0 = g_hlo + (size_t)(parity ^ 1) * BATCH * DH;
        const int rL = lane >> 2, cL = (lane & 3) * 2;
        #pragma unroll
        for (int tm = 0; tm < 2; tm++)
            #pragma unroll
            for (int nt = 0; nt < 4; nt++) {
                const int col = n0 + wn * 32 + nt * 8 + cL;
                #pragma unroll
                for (int hf = 0; hf < 2; hf++) {
                    const int row = m0 + tm * 16 + rL + hf * 8;
                    const int o = tm * 16 + nt * 4 + hf * 2;
                    const size_t zi = ((size_t)t * BATCH + row) * DH + col;
                    const float2 zv = *(const float2*)(g_Z + zi);
                    float z0 = s[o]   + zv.x;
                    float z1 = s[o+1] + zv.y;
                    float e0 = __expf(2.0f * z0), e1 = __expf(2.0f * z1);
                    float h0 = 1.0f - 2.0f / (e0 + 1.0f);
                    float h1 = 1.0f - 2.0f / (e1 + 1.0f);
                    *(float2*)(outNext + (size_t)row * DH + col) = make_float2(h0, h1);
                    __nv_bfloat16 p0 = __float2bfloat16(h0), p1 = __float2bfloat16(h1);
                    __nv_bfloat162 hi2; hi2.x = p0; hi2.y = p1;
                    __nv_bfloat162 lo2;
                    lo2.x = __float2bfloat16(h0 - __bfloat162float(p0));
                    lo2.y = __float2bfloat16(h1 - __bfloat162float(p1));
                    *(__nv_bfloat162*)(hh0 + (size_t)row * DH + col) = hi2;
                    *(__nv_bfloat162*)(hl0 + (size_t)row * DH + col) = lo2;
                }
            }
    }
}

extern "C" void kernel_launch(void* const* d_in, const int* in_sizes, int n_in,
                              void* d_out, int out_size) {
    const float* seq = (const float*)d_in[0];   // (T, B, DIN)
    const float* W   = (const float*)d_in[1];   // (DH, KTOT)
    const float* b   = (const float*)d_in[2];   // (DH,)
    float* out = (float*)d_out;                 // (T+1, B, DH)
    (void)in_sizes; (void)n_in; (void)out_size;

    cudaFuncSetAttribute(precompute_z, cudaFuncAttributeMaxDynamicSharedMemorySize, SMEM2);
    cudaFuncSetAttribute(rnn_step, cudaFuncAttributeMaxDynamicSharedMemorySize, SMEM1);

    const size_t slice = (size_t)BATCH * DH;

    split_w<<<(DH * KTOT) / 256, 256>>>(W);
    split_x<<<(TSTEPS * BATCH * DIN) / 256, 256>>>(seq);
    init_out0<<<(BATCH * DH) / 256, 256>>>(out);

    dim3 pgrid(DH / 64, (TSTEPS * BATCH) / 128);   // (16, 512)
    precompute_z<<<pgrid, 256, SMEM2>>>(b);

    dim3 grid(16, 8);                               // 128 CTAs
    for (int t = 0; t < TSTEPS; t++) {
        rnn_step<<<grid, 256, SMEM1>>>(out + (t + 1) * slice, t, t & 1);
    }
}

// round 10
// speedup vs baseline: 1.2110x; 1.2110x over previous
#include <cuda_runtime.h>
#include <cuda_bf16.h>
#include <cstdint>

// RNN_438086664357: h_{t+1} = tanh(W [h_t ; x_t] + b)
// Round 9: Z precomputed (proven 67% tensor kernel); steps run in ONE
// persistent kernel (128 co-resident CTAs) with a minimal release-counter
// grid barrier per step. Mainloop/epilogue identical to R7 (proven fastest).

#define TSTEPS 256
#define BATCH  256
#define DH     1024
#define DIN    1024
#define KTOT   2048
#define KC     64
#define NCH    16              // K=1024 / 64
#define NCTA   128

typedef unsigned int u32;

// step stage: Ahi 4K | Alo 4K | Whi 8K | Wlo 8K
#define SOFF_ALO  4096
#define SOFF_WHI  8192
#define SOFF_WLO  16384
#define STG1      24576
#define SMEM1     (3 * STG1)      // 72 KB

// precompute stage: Ahi 16K | Alo 16K | Whi 8K | Wlo 8K
#define SOFF2_ALO 16384
#define SOFF2_WHI 32768
#define SOFF2_WLO 40960
#define STG2      49152
#define SMEM2     (3 * STG2)      // 144 KB

// ---- device scratch ----
__device__ __nv_bfloat16 g_xhi[(size_t)TSTEPS * BATCH * DIN];
__device__ __nv_bfloat16 g_xlo[(size_t)TSTEPS * BATCH * DIN];
__device__ __nv_bfloat16 g_whi[(size_t)DH * KTOT];
__device__ __nv_bfloat16 g_wlo[(size_t)DH * KTOT];
__device__ __nv_bfloat16 g_hhi[2 * (size_t)BATCH * DH];
__device__ __nv_bfloat16 g_hlo[2 * (size_t)BATCH * DH];
__device__ float g_Z[(size_t)TSTEPS * BATCH * DH];
__device__ unsigned g_bar;

__device__ __forceinline__ u32 s2u(const void* p) {
    u32 a;
    asm("{ .reg .u64 t; cvta.to.shared.u64 t, %1; cvt.u32.u64 %0, t; }"
        : "=r"(a) : "l"(p));
    return a;
}

#define CP16(sm, gp) asm volatile("cp.async.cg.shared.global [%0], [%1], 16;" :: "r"(sm), "l"(gp))
#define CP_COMMIT()  asm volatile("cp.async.commit_group;" ::: "memory")

__device__ __forceinline__ void ldsm4(u32 a, u32& r0, u32& r1, u32& r2, u32& r3) {
    asm volatile("ldmatrix.sync.aligned.m8n8.x4.shared.b16 {%0,%1,%2,%3}, [%4];"
                 : "=r"(r0), "=r"(r1), "=r"(r2), "=r"(r3) : "r"(a));
}

__device__ __forceinline__ void mma16816(float* c, const u32* a, u32 b0, u32 b1) {
    asm volatile(
        "mma.sync.aligned.m16n8k16.row.col.f32.bf16.bf16.f32 "
        "{%0,%1,%2,%3}, {%4,%5,%6,%7}, {%8,%9}, {%0,%1,%2,%3};"
        : "+f"(c[0]), "+f"(c[1]), "+f"(c[2]), "+f"(c[3])
        : "r"(a[0]), "r"(a[1]), "r"(a[2]), "r"(a[3]), "r"(b0), "r"(b1));
}

// ---- setup kernels ----
__global__ void split_w(const float* __restrict__ W) {
    int i = blockIdx.x * blockDim.x + threadIdx.x;
    float v = W[i];
    __nv_bfloat16 h = __float2bfloat16(v);
    g_whi[i] = h;
    g_wlo[i] = __float2bfloat16(v - __bfloat162float(h));
}

__global__ void split_x(const float* __restrict__ X) {
    size_t i = (size_t)blockIdx.x * blockDim.x + threadIdx.x;
    float v = X[i];
    __nv_bfloat16 h = __float2bfloat16(v);
    g_xhi[i] = h;
    g_xlo[i] = __float2bfloat16(v - __bfloat162float(h));
}

__global__ void init_out0(float* __restrict__ out0) {
    out0[blockIdx.x * blockDim.x + threadIdx.x] = 0.0f;
    if (blockIdx.x == 0 && threadIdx.x == 0) g_bar = 0u;
}

// ---- precompute Z = x @ Wx^T + b (proven: 67% tensor) ----
__global__ void __launch_bounds__(256, 1)
precompute_z(const float* __restrict__ bias)
{
    extern __shared__ char smem[];
    const u32 sb = s2u(smem);
    const int tid = threadIdx.x, wid = tid >> 5, lane = tid & 31;
    const int wm = wid & 3, wn = wid >> 2;
    const int n0 = blockIdx.x * 64;
    const int mg = blockIdx.y * 128;

    auto load_chunk = [&](int c, int s) {
        const u32 st = sb + s * STG2;
        const int ko = c * KC;
        #pragma unroll
        for (int i = 0; i < 4; i++) {
            int unit = tid + i * 256;
            int r = unit >> 3, g = unit & 7;
            u32 so = (u32)(r * 128 + ((g ^ (r & 7)) * 16));
            size_t go = (size_t)(mg + r) * DIN + ko + g * 8;
            CP16(st + so,             g_xhi + go);
            CP16(st + SOFF2_ALO + so, g_xlo + go);
        }
        #pragma unroll
        for (int i = 0; i < 2; i++) {
            int unit = tid + i * 256;
            int r = unit >> 3, g = unit & 7;
            u32 so = (u32)(r * 128 + ((g ^ (r & 7)) * 16));
            size_t go = (size_t)(n0 + r) * KTOT + DH + ko + g * 8;
            CP16(st + SOFF2_WHI + so, g_whi + go);
            CP16(st + SOFF2_WLO + so, g_wlo + go);
        }
        CP_COMMIT();
    };

    float c0[32], c1[32], c2[32];
    #pragma unroll
    for (int i = 0; i < 32; i++) { c0[i] = 0.f; c1[i] = 0.f; c2[i] = 0.f; }

    load_chunk(0, 0);
    load_chunk(1, 1);
    for (int c = 0; c < 16; c++) {
        if (c < 15) asm volatile("cp.async.wait_group 1;" ::: "memory");
        else        asm volatile("cp.async.wait_group 0;" ::: "memory");
        __syncthreads();
        const u32 st = sb + (c % 3) * STG2;
        #pragma unroll
        for (int j = 0; j < 4; j++) {
            u32 ah[2][4], al[2][4], bh[8], bl[8];
            #pragma unroll
            for (int tm = 0; tm < 2; tm++) {
                int row = wm * 32 + tm * 16 + (lane & 15);
                int g = j * 2 + (lane >> 4);
                u32 so = (u32)(row * 128 + ((g ^ (row & 7)) * 16));
                ldsm4(st + so,             ah[tm][0], ah[tm][1], ah[tm][2], ah[tm][3]);
                ldsm4(st + SOFF2_ALO + so, al[tm][0], al[tm][1], al[tm][2], al[tm][3]);
            }
            int rB = wn * 32 + (lane & 7) + ((lane >> 4) & 1) * 8;
            int gB = j * 2 + ((lane >> 3) & 1);
            #pragma unroll
            for (int q = 0; q < 2; q++) {
                int r = rB + q * 16;
                u32 so = (u32)(r * 128 + ((gB ^ (r & 7)) * 16));
                ldsm4(st + SOFF2_WHI + so, bh[q*4+0], bh[q*4+1], bh[q*4+2], bh[q*4+3]);
                ldsm4(st + SOFF2_WLO + so, bl[q*4+0], bl[q*4+1], bl[q*4+2], bl[q*4+3]);
            }
            #pragma unroll
            for (int tm = 0; tm < 2; tm++)
                #pragma unroll
                for (int nt = 0; nt < 4; nt++) {
                    int o = tm * 16 + nt * 4;
                    mma16816(c0 + o, ah[tm], bh[nt*2], bh[nt*2+1]);
                    mma16816(c1 + o, al[tm], bh[nt*2], bh[nt*2+1]);
                    mma16816(c2 + o, ah[tm], bl[nt*2], bl[nt*2+1]);
                }
        }
        if (c + 2 < 16) load_chunk(c + 2, (c + 2) % 3);
    }

    #pragma unroll
    for (int tm = 0; tm < 2; tm++)
        #pragma unroll
        for (int nt = 0; nt < 4; nt++) {
            const int col = n0 + wn * 32 + nt * 8 + (lane & 3) * 2;
            const float b0 = __ldg(bias + col), b1 = __ldg(bias + col + 1);
            #pragma unroll
            for (int hf = 0; hf < 2; hf++) {
                const int row = mg + wm * 32 + tm * 16 + (lane >> 2) + hf * 8;
                const int o = tm * 16 + nt * 4 + hf * 2;
                float z0 = c0[o]   + c1[o]   + c2[o]   + b0;
                float z1 = c0[o+1] + c1[o+1] + c2[o+1] + b1;
                *(float2*)(g_Z + (size_t)row * DH + col) = make_float2(z0, z1);
            }
        }
}

// ---- persistent step engine: R7 mainloop + minimal grid barrier ----
// grid (16 n, 8 m) = 128 CTAs; CTA tile (32m, 64n); 4 warps 2x2, m16n32.
__global__ void __launch_bounds__(128, 1)
rnn_persist(float* __restrict__ out)
{
    extern __shared__ char smem[];
    const u32 sb = s2u(smem);
    const int tid = threadIdx.x, wid = tid >> 5, lane = tid & 31;
    const int wm = wid & 1, wn = wid >> 1;
    const int n0 = blockIdx.x * 64, m0 = blockIdx.y * 32;
    const int lr = tid >> 3, lg = tid & 7;
    const size_t slice = (size_t)BATCH * DH;

    const int aRow  = wm * 16 + (lane & 15);
    const int aHi   = (lane >> 4);
    const int bRow0 = wn * 32 + (lane & 7) + ((lane >> 4) & 1) * 8;
    const int bHi   = (lane >> 3) & 1;
    const int rL = lane >> 2, cL = (lane & 3) * 2;

    for (int t = 0; t < TSTEPS; t++) {
        const int parity = t & 1;
        float c0[16], c1[16], c2[16];
        #pragma unroll
        for (int i = 0; i < 16; i++) { c0[i] = 0.f; c1[i] = 0.f; c2[i] = 0.f; }

        if (t > 0) {
            const __nv_bfloat16* Ahi0 = g_hhi + (size_t)parity * slice;
            const __nv_bfloat16* Alo0 = g_hlo + (size_t)parity * slice;

            auto load_chunk = [&](int c, int s) {
                const u32 st = sb + s * STG1;
                const int ko = c * KC;
                #pragma unroll
                for (int u = 0; u < 2; u++) {
                    int r = lr + u * 16;
                    u32 so = (u32)(r * 128 + ((lg ^ (r & 7)) * 16));
                    size_t go = (size_t)(m0 + r) * DH + ko + lg * 8;
                    CP16(st + so,            Ahi0 + go);
                    CP16(st + SOFF_ALO + so, Alo0 + go);
                }
                #pragma unroll
                for (int u = 0; u < 4; u++) {
                    int r = lr + u * 16;
                    u32 so = (u32)(r * 128 + ((lg ^ (r & 7)) * 16));
                    size_t go = (size_t)(n0 + r) * KTOT + ko + lg * 8;
                    CP16(st + SOFF_WHI + so, g_whi + go);
                    CP16(st + SOFF_WLO + so, g_wlo + go);
                }
                CP_COMMIT();
            };

            load_chunk(0, 0);
            load_chunk(1, 1);
            for (int c = 0; c < NCH; c++) {
                if (c < NCH - 1) asm volatile("cp.async.wait_group 1;" ::: "memory");
                else             asm volatile("cp.async.wait_group 0;" ::: "memory");
                __syncthreads();
                const u32 st = sb + (c % 3) * STG1;
                #pragma unroll
                for (int j = 0; j < 4; j++) {
                    u32 ah[4], al[4], bh[8], bl[8];
                    {
                        int g = j * 2 + aHi;
                        u32 so = (u32)(aRow * 128 + ((g ^ (aRow & 7)) * 16));
                        ldsm4(st + so,            ah[0], ah[1], ah[2], ah[3]);
                        ldsm4(st + SOFF_ALO + so, al[0], al[1], al[2], al[3]);
                    }
                    #pragma unroll
                    for (int q = 0; q < 2; q++) {
                        int r = bRow0 + q * 16;
                        int g = j * 2 + bHi;
                        u32 so = (u32)(r * 128 + ((g ^ (r & 7)) * 16));
                        ldsm4(st + SOFF_WHI + so, bh[q*4+0], bh[q*4+1], bh[q*4+2], bh[q*4+3]);
                        ldsm4(st + SOFF_WLO + so, bl[q*4+0], bl[q*4+1], bl[q*4+2], bl[q*4+3]);
                    }
                    #pragma unroll
                    for (int nt = 0; nt < 4; nt++) {
                        mma16816(c0 + nt * 4, ah, bh[nt*2], bh[nt*2+1]);
                        mma16816(c1 + nt * 4, al, bh[nt*2], bh[nt*2+1]);
                        mma16816(c2 + nt * 4, ah, bl[nt*2], bl[nt*2+1]);
                    }
                }
                if (c + 2 < NCH) load_chunk(c + 2, (c + 2) % 3);
            }
        }

        // epilogue: h' = tanh(acc + Z[t]); fp32 out + bf16 hi/lo state
        {
            float* outN = out + (size_t)(t + 1) * slice;
            __nv_bfloat16* hh0 = g_hhi + (size_t)(parity ^ 1) * slice;
            __nv_bfloat16* hl0 = g_hlo + (size_t)(parity ^ 1) * slice;
            #pragma unroll
            for (int nt = 0; nt < 4; nt++) {
                const int col = n0 + wn * 32 + nt * 8 + cL;
                #pragma unroll
                for (int hf = 0; hf < 2; hf++) {
                    const int row = m0 + wm * 16 + rL + hf * 8;
                    const int o = nt * 4 + hf * 2;
                    const size_t zi = ((size_t)t * BATCH + row) * DH + col;
                    const float2 zv = *(const float2*)(g_Z + zi);
                    float z0 = c0[o]   + c1[o]   + c2[o]   + zv.x;
                    float z1 = c0[o+1] + c1[o+1] + c2[o+1] + zv.y;
                    float e0 = __expf(2.0f * z0), e1 = __expf(2.0f * z1);
                    float h0 = 1.0f - 2.0f / (e0 + 1.0f);
                    float h1 = 1.0f - 2.0f / (e1 + 1.0f);
                    *(float2*)(outN + (size_t)row * DH + col) = make_float2(h0, h1);
                    __nv_bfloat16 p0 = __float2bfloat16(h0), p1 = __float2bfloat16(h1);
                    __nv_bfloat162 hi2; hi2.x = p0; hi2.y = p1;
                    __nv_bfloat162 lo2;
                    lo2.x = __float2bfloat16(h0 - __bfloat162float(p0));
                    lo2.y = __float2bfloat16(h1 - __bfloat162float(p1));
                    *(__nv_bfloat162*)(hh0 + (size_t)row * DH + col) = hi2;
                    *(__nv_bfloat162*)(hl0 + (size_t)row * DH + col) = lo2;
                }
            }
        }

        // grid barrier (skip after last step)
        if (t != TSTEPS - 1) {
            __syncthreads();               // all CTA writes issued
            if (tid == 0) {
                asm volatile("red.release.gpu.global.add.u32 [%0], 1;"
                             :: "l"(&g_bar) : "memory");
                const unsigned tgt = (unsigned)NCTA * (unsigned)(t + 1);
                unsigned v;
                do {
                    asm volatile("ld.acquire.gpu.global.u32 %0, [%1];"
                                 : "=r"(v) : "l"(&g_bar) : "memory");
                    if (v < tgt) asm volatile("nanosleep.u32 64;");
                } while (v < tgt);
            }
            __syncthreads();               // release visibility to whole CTA
        }
    }
}

extern "C" void kernel_launch(void* const* d_in, const int* in_sizes, int n_in,
                              void* d_out, int out_size) {
    const float* seq = (const float*)d_in[0];   // (T, B, DIN)
    const float* W   = (const float*)d_in[1];   // (DH, KTOT)
    const float* b   = (const float*)d_in[2];   // (DH,)
    float* out = (float*)d_out;                 // (T+1, B, DH)
    (void)in_sizes; (void)n_in; (void)out_size;

    cudaFuncSetAttribute(precompute_z, cudaFuncAttributeMaxDynamicSharedMemorySize, SMEM2);
    cudaFuncSetAttribute(rnn_persist, cudaFuncAttributeMaxDynamicSharedMemorySize, SMEM1);

    split_w<<<(DH * KTOT) / 256, 256>>>(W);
    split_x<<<(TSTEPS * BATCH * DIN) / 256, 256>>>(seq);
    init_out0<<<(BATCH * DH) / 256, 256>>>(out);

    dim3 pgrid(DH / 64, (TSTEPS * BATCH) / 128);   // (16, 512)
    precompute_z<<<pgrid, 256, SMEM2>>>(b);

    dim3 grid(16, 8);                               // 128 CTAs, 1/SM
    rnn_persist<<<grid, 128, SMEM1>>>(out);
}

// round 13
// speedup vs baseline: 1.3103x; 1.0820x over previous
#include <cuda_runtime.h>
#include <cuda_bf16.h>
#include <cstdint>

// RNN_438086664357: h_{t+1} = tanh(W [h_t ; x_t] + b)
// Round 10: persistent engine + Whi resident in smem (128KB, loaded once),
// 8 warps (2/SMSP) with in-CTA split-K=2 and tiny smem reduction.
// Z = x@Wx^T+b precomputed (proven 67%-tensor kernel).

#define TSTEPS 256
#define BATCH  256
#define DH     1024
#define DIN    1024
#define KTOT   2048
#define KC     64
#define NCH    16              // K=1024 / 64
#define NCTA   128

typedef unsigned int u32;

// persistent kernel smem layout
#define SM_WHI  0              // 16 panels x 8KB = 128KB (resident)
#define SM_WLO  131072         // 3 stages x 8KB
#define SM_A    155648         // 3 stages x (Ahi 4K | Alo 4K)
#define SM_RED  180224         // 8KB reduction
#define SMEM1   188416

// precompute stage: Ahi 16K | Alo 16K | Whi 8K | Wlo 8K
#define SOFF2_ALO 16384
#define SOFF2_WHI 32768
#define SOFF2_WLO 40960
#define STG2      49152
#define SMEM2     (3 * STG2)

// ---- device scratch ----
__device__ __nv_bfloat16 g_xhi[(size_t)TSTEPS * BATCH * DIN];
__device__ __nv_bfloat16 g_xlo[(size_t)TSTEPS * BATCH * DIN];
__device__ __nv_bfloat16 g_whi[(size_t)DH * KTOT];
__device__ __nv_bfloat16 g_wlo[(size_t)DH * KTOT];
__device__ __nv_bfloat16 g_hhi[2 * (size_t)BATCH * DH];
__device__ __nv_bfloat16 g_hlo[2 * (size_t)BATCH * DH];
__device__ float g_Z[(size_t)TSTEPS * BATCH * DH];
__device__ unsigned g_bar;

__device__ __forceinline__ u32 s2u(const void* p) {
    u32 a;
    asm("{ .reg .u64 t; cvta.to.shared.u64 t, %1; cvt.u32.u64 %0, t; }"
        : "=r"(a) : "l"(p));
    return a;
}

#define CP16(sm, gp) asm volatile("cp.async.cg.shared.global [%0], [%1], 16;" :: "r"(sm), "l"(gp))
#define CP_COMMIT()  asm volatile("cp.async.commit_group;" ::: "memory")

__device__ __forceinline__ void ldsm4(u32 a, u32& r0, u32& r1, u32& r2, u32& r3) {
    asm volatile("ldmatrix.sync.aligned.m8n8.x4.shared.b16 {%0,%1,%2,%3}, [%4];"
                 : "=r"(r0), "=r"(r1), "=r"(r2), "=r"(r3) : "r"(a));
}

__device__ __forceinline__ void mma16816(float* c, const u32* a, u32 b0, u32 b1) {
    asm volatile(
        "mma.sync.aligned.m16n8k16.row.col.f32.bf16.bf16.f32 "
        "{%0,%1,%2,%3}, {%4,%5,%6,%7}, {%8,%9}, {%0,%1,%2,%3};"
        : "+f"(c[0]), "+f"(c[1]), "+f"(c[2]), "+f"(c[3])
        : "r"(a[0]), "r"(a[1]), "r"(a[2]), "r"(a[3]), "r"(b0), "r"(b1));
}

// ---- setup kernels ----
__global__ void split_w(const float* __restrict__ W) {
    int i = blockIdx.x * blockDim.x + threadIdx.x;
    float v = W[i];
    __nv_bfloat16 h = __float2bfloat16(v);
    g_whi[i] = h;
    g_wlo[i] = __float2bfloat16(v - __bfloat162float(h));
}

__global__ void split_x(const float* __restrict__ X) {
    size_t i = (size_t)blockIdx.x * blockDim.x + threadIdx.x;
    float v = X[i];
    __nv_bfloat16 h = __float2bfloat16(v);
    g_xhi[i] = h;
    g_xlo[i] = __float2bfloat16(v - __bfloat162float(h));
}

__global__ void init_out0(float* __restrict__ out0) {
    out0[blockIdx.x * blockDim.x + threadIdx.x] = 0.0f;
    if (blockIdx.x == 0 && threadIdx.x == 0) g_bar = 0u;
}

// ---- precompute Z = x @ Wx^T + b (proven: 67% tensor) ----
__global__ void __launch_bounds__(256, 1)
precompute_z(const float* __restrict__ bias)
{
    extern __shared__ char smem[];
    const u32 sb = s2u(smem);
    const int tid = threadIdx.x, wid = tid >> 5, lane = tid & 31;
    const int wm = wid & 3, wn = wid >> 2;
    const int n0 = blockIdx.x * 64;
    const int mg = blockIdx.y * 128;

    auto load_chunk = [&](int c, int s) {
        const u32 st = sb + s * STG2;
        const int ko = c * KC;
        #pragma unroll
        for (int i = 0; i < 4; i++) {
            int unit = tid + i * 256;
            int r = unit >> 3, g = unit & 7;
            u32 so = (u32)(r * 128 + ((g ^ (r & 7)) * 16));
            size_t go = (size_t)(mg + r) * DIN + ko + g * 8;
            CP16(st + so,             g_xhi + go);
            CP16(st + SOFF2_ALO + so, g_xlo + go);
        }
        #pragma unroll
        for (int i = 0; i < 2; i++) {
            int unit = tid + i * 256;
            int r = unit >> 3, g = unit & 7;
            u32 so = (u32)(r * 128 + ((g ^ (r & 7)) * 16));
            size_t go = (size_t)(n0 + r) * KTOT + DH + ko + g * 8;
            CP16(st + SOFF2_WHI + so, g_whi + go);
            CP16(st + SOFF2_WLO + so, g_wlo + go);
        }
        CP_COMMIT();
    };

    float c0[32], c1[32], c2[32];
    #pragma unroll
    for (int i = 0; i < 32; i++) { c0[i] = 0.f; c1[i] = 0.f; c2[i] = 0.f; }

    load_chunk(0, 0);
    load_chunk(1, 1);
    for (int c = 0; c < 16; c++) {
        if (c < 15) asm volatile("cp.async.wait_group 1;" ::: "memory");
        else        asm volatile("cp.async.wait_group 0;" ::: "memory");
        __syncthreads();
        const u32 st = sb + (c % 3) * STG2;
        #pragma unroll
        for (int j = 0; j < 4; j++) {
            u32 ah[2][4], al[2][4], bh[8], bl[8];
            #pragma unroll
            for (int tm = 0; tm < 2; tm++) {
                int row = wm * 32 + tm * 16 + (lane & 15);
                int g = j * 2 + (lane >> 4);
                u32 so = (u32)(row * 128 + ((g ^ (row & 7)) * 16));
                ldsm4(st + so,             ah[tm][0], ah[tm][1], ah[tm][2], ah[tm][3]);
                ldsm4(st + SOFF2_ALO + so, al[tm][0], al[tm][1], al[tm][2], al[tm][3]);
            }
            int rB = wn * 32 + (lane & 7) + ((lane >> 4) & 1) * 8;
            int gB = j * 2 + ((lane >> 3) & 1);
            #pragma unroll
            for (int q = 0; q < 2; q++) {
                int r = rB + q * 16;
                u32 so = (u32)(r * 128 + ((gB ^ (r & 7)) * 16));
                ldsm4(st + SOFF2_WHI + so, bh[q*4+0], bh[q*4+1], bh[q*4+2], bh[q*4+3]);
                ldsm4(st + SOFF2_WLO + so, bl[q*4+0], bl[q*4+1], bl[q*4+2], bl[q*4+3]);
            }
            #pragma unroll
            for (int tm = 0; tm < 2; tm++)
                #pragma unroll
                for (int nt = 0; nt < 4; nt++) {
                    int o = tm * 16 + nt * 4;
                    mma16816(c0 + o, ah[tm], bh[nt*2], bh[nt*2+1]);
                    mma16816(c1 + o, al[tm], bh[nt*2], bh[nt*2+1]);
                    mma16816(c2 + o, ah[tm], bl[nt*2], bl[nt*2+1]);
                }
        }
        if (c + 2 < 16) load_chunk(c + 2, (c + 2) % 3);
    }

    #pragma unroll
    for (int tm = 0; tm < 2; tm++)
        #pragma unroll
        for (int nt = 0; nt < 4; nt++) {
            const int col = n0 + wn * 32 + nt * 8 + (lane & 3) * 2;
            const float b0 = __ldg(bias + col), b1 = __ldg(bias + col + 1);
            #pragma unroll
            for (int hf = 0; hf < 2; hf++) {
                const int row = mg + wm * 32 + tm * 16 + (lane >> 2) + hf * 8;
                const int o = tm * 16 + nt * 4 + hf * 2;
                float z0 = c0[o]   + c1[o]   + c2[o]   + b0;
                float z1 = c0[o+1] + c1[o+1] + c2[o+1] + b1;
                *(float2*)(g_Z + (size_t)row * DH + col) = make_float2(z0, z1);
            }
        }
}

// ---- persistent step engine ----
// grid (16 n, 8 m) = 128 CTAs; CTA tile (32m, 64n); 256 threads:
// wk = wid>>2 (2 k-groups, j = wk*2+jj), wq = wid&3 -> 2x2 m16n32 tiles.
// Whi resident in smem; A + Wlo streamed (3-stage cp.async).
__global__ void __launch_bounds__(256, 1)
rnn_persist(float* __restrict__ out)
{
    extern __shared__ char smem[];
    const u32 sb = s2u(smem);
    const int tid = threadIdx.x, wid = tid >> 5, lane = tid & 31;
    const int wk = wid >> 2, wq = wid & 3;
    const int wm = wq & 1, wn = wq >> 1;
    const int n0 = blockIdx.x * 64, m0 = blockIdx.y * 32;
    const int lr = tid >> 3, lg = tid & 7;   // 256 thr: 32 rows x 8 groups
    const size_t slice = (size_t)BATCH * DH;

    // per-warp constant fragment addressing (j = wk*2 + jj)
    const int aRow  = wm * 16 + (lane & 15);
    const int aHi   = (lane >> 4);
    const int bRow0 = wn * 32 + (lane & 7) + ((lane >> 4) & 1) * 8;
    const int bHi   = (lane >> 3) & 1;
    const int rL = lane >> 2, cL = (lane & 3) * 2;

    // ---- preload resident Whi: 16 panels x (64 rows x 64 cols) ----
    #pragma unroll
    for (int i = 0; i < 32; i++) {
        int u = tid + i * 256;                  // 0..8191 16B units
        int p = u >> 9, r = (u >> 3) & 63, g = u & 7;
        u32 so = (u32)(p * 8192 + r * 128 + ((g ^ (r & 7)) * 16));
        size_t go = (size_t)(n0 + r) * KTOT + p * 64 + g * 8;
        CP16(sb + SM_WHI + so, g_whi + go);
    }
    CP_COMMIT();
    asm volatile("cp.async.wait_group 0;" ::: "memory");
    __syncthreads();

    for (int t = 0; t < TSTEPS; t++) {
        const int parity = t & 1;
        float s[16];

        if (t > 0) {
            const __nv_bfloat16* Ahi0 = g_hhi + (size_t)parity * slice;
            const __nv_bfloat16* Alo0 = g_hlo + (size_t)parity * slice;

            auto load_chunk = [&](int c) {
                const int si = c % 3;
                const int ko = c * KC;
                {   // A: 32 rows, 1 unit/thread per buffer
                    u32 so = (u32)(lr * 128 + ((lg ^ (lr & 7)) * 16));
                    size_t go = (size_t)(m0 + lr) * DH + ko + lg * 8;
                    CP16(sb + SM_A + si * 8192 + so,        Ahi0 + go);
                    CP16(sb + SM_A + si * 8192 + 4096 + so, Alo0 + go);
                }
                #pragma unroll
                for (int u = 0; u < 2; u++) {   // Wlo: 64 rows, 2 units/thread
                    int r = lr + u * 32;
                    u32 so = (u32)(r * 128 + ((lg ^ (r & 7)) * 16));
                    size_t go = (size_t)(n0 + r) * KTOT + ko + lg * 8;
                    CP16(sb + SM_WLO + si * 8192 + so, g_wlo + go);
                }
                CP_COMMIT();
            };

            float c0[16], c1[16], c2[16];
            #pragma unroll
            for (int i = 0; i < 16; i++) { c0[i] = 0.f; c1[i] = 0.f; c2[i] = 0.f; }

            load_chunk(0);
            load_chunk(1);
            for (int c = 0; c < NCH; c++) {
                if (c < NCH - 1) asm volatile("cp.async.wait_group 1;" ::: "memory");
                else             asm volatile("cp.async.wait_group 0;" ::: "memory");
                __syncthreads();
                const u32 stA  = sb + SM_A + (c % 3) * 8192;
                const u32 stWl = sb + SM_WLO + (c % 3) * 8192;
                const u32 pW   = sb + SM_WHI + c * 8192;
                #pragma unroll
                for (int jj = 0; jj < 2; jj++) {
                    const int j = wk * 2 + jj;
                    u32 ah[4], al[4], bh[8], bl[8];
                    {
                        int g = j * 2 + aHi;
                        u32 so = (u32)(aRow * 128 + ((g ^ (aRow & 7)) * 16));
                        ldsm4(stA + so,        ah[0], ah[1], ah[2], ah[3]);
                        ldsm4(stA + 4096 + so, al[0], al[1], al[2], al[3]);
                    }
                    #pragma unroll
                    for (int q = 0; q < 2; q++) {
                        int r = bRow0 + q * 16;
                        int g = j * 2 + bHi;
                        u32 so = (u32)(r * 128 + ((g ^ (r & 7)) * 16));
                        ldsm4(pW + so,   bh[q*4+0], bh[q*4+1], bh[q*4+2], bh[q*4+3]);
                        ldsm4(stWl + so, bl[q*4+0], bl[q*4+1], bl[q*4+2], bl[q*4+3]);
                    }
                    #pragma unroll
                    for (int nt = 0; nt < 4; nt++) {
                        mma16816(c0 + nt * 4, ah, bh[nt*2], bh[nt*2+1]);
                        mma16816(c1 + nt * 4, al, bh[nt*2], bh[nt*2+1]);
                        mma16816(c2 + nt * 4, ah, bl[nt*2], bl[nt*2+1]);
                    }
                }
                if (c + 2 < NCH) load_chunk(c + 2);
            }

            #pragma unroll
            for (int i = 0; i < 16; i++) s[i] = c0[i] + c1[i] + c2[i];

            // split-K reduction: wk=1 publishes, wk=0 folds
            float* red = (float*)(smem + SM_RED);
            if (wk == 1) {
                float* dst = red + ((wq * 32 + lane) * 16);
                #pragma unroll
                for (int i = 0; i < 4; i++)
                    *(float4*)(dst + i * 4) =
                        make_float4(s[i*4], s[i*4+1], s[i*4+2], s[i*4+3]);
            }
            __syncthreads();
            if (wk == 0) {
                const float* src = red + ((wq * 32 + lane) * 16);
                #pragma unroll
                for (int i = 0; i < 4; i++) {
                    float4 v = *(const float4*)(src + i * 4);
                    s[i*4] += v.x; s[i*4+1] += v.y; s[i*4+2] += v.z; s[i*4+3] += v.w;
                }
            }
        } else {
            #pragma unroll
            for (int i = 0; i < 16; i++) s[i] = 0.f;
        }

        // epilogue (wk==0 warps = full 2x2 tile coverage)
        if (wk == 0) {
            float* outN = out + (size_t)(t + 1) * slice;
            __nv_bfloat16* hh0 = g_hhi + (size_t)(parity ^ 1) * slice;
            __nv_bfloat16* hl0 = g_hlo + (size_t)(parity ^ 1) * slice;
            #pragma unroll
            for (int nt = 0; nt < 4; nt++) {
                const int col = n0 + wn * 32 + nt * 8 + cL;
                #pragma unroll
                for (int hf = 0; hf < 2; hf++) {
                    const int row = m0 + wm * 16 + rL + hf * 8;
                    const int o = nt * 4 + hf * 2;
                    const size_t zi = ((size_t)t * BATCH + row) * DH + col;
                    const float2 zv = *(const float2*)(g_Z + zi);
                    float z0 = s[o]   + zv.x;
                    float z1 = s[o+1] + zv.y;
                    float e0 = __expf(2.0f * z0), e1 = __expf(2.0f * z1);
                    float h0 = 1.0f - 2.0f / (e0 + 1.0f);
                    float h1 = 1.0f - 2.0f / (e1 + 1.0f);
                    *(float2*)(outN + (size_t)row * DH + col) = make_float2(h0, h1);
                    __nv_bfloat16 p0 = __float2bfloat16(h0), p1 = __float2bfloat16(h1);
                    __nv_bfloat162 hi2; hi2.x = p0; hi2.y = p1;
                    __nv_bfloat162 lo2;
                    lo2.x = __float2bfloat16(h0 - __bfloat162float(p0));
                    lo2.y = __float2bfloat16(h1 - __bfloat162float(p1));
                    *(__nv_bfloat162*)(hh0 + (size_t)row * DH + col) = hi2;
                    *(__nv_bfloat162*)(hl0 + (size_t)row * DH + col) = lo2;
                }
            }
        }

        // grid barrier (skip after last step)
        if (t != TSTEPS - 1) {
            __syncthreads();
            if (tid == 0) {
                asm volatile("red.release.gpu.global.add.u32 [%0], 1;"
                             :: "l"(&g_bar) : "memory");
                const unsigned tgt = (unsigned)NCTA * (unsigned)(t + 1);
                unsigned v;
                do {
                    asm volatile("ld.acquire.gpu.global.u32 %0, [%1];"
                                 : "=r"(v) : "l"(&g_bar) : "memory");
                    if (v < tgt) asm volatile("nanosleep.u32 64;");
                } while (v < tgt);
            }
            __syncthreads();
        }
    }
}

extern "C" void kernel_launch(void* const* d_in, const int* in_sizes, int n_in,
                              void* d_out, int out_size) {
    const float* seq = (const float*)d_in[0];   // (T, B, DIN)
    const float* W   = (const float*)d_in[1];   // (DH, KTOT)
    const float* b   = (const float*)d_in[2];   // (DH,)
    float* out = (float*)d_out;                 // (T+1, B, DH)
    (void)in_sizes; (void)n_in; (void)out_size;

    cudaFuncSetAttribute(precompute_z, cudaFuncAttributeMaxDynamicSharedMemorySize, SMEM2);
    cudaFuncSetAttribute(rnn_persist, cudaFuncAttributeMaxDynamicSharedMemorySize, SMEM1);

    split_w<<<(DH * KTOT) / 256, 256>>>(W);
    split_x<<<(TSTEPS * BATCH * DIN) / 256, 256>>>(seq);
    init_out0<<<(BATCH * DH) / 256, 256>>>(out);

    dim3 pgrid(DH / 64, (TSTEPS * BATCH) / 128);   // (16, 512)
    precompute_z<<<pgrid, 256, SMEM2>>>(b);

    dim3 grid(16, 8);                               // 128 CTAs, 1/SM
    rnn_persist<<<grid, 256, SMEM1>>>(out);
}